// round 4
// baseline (speedup 1.0000x reference)
#include <cuda_runtime.h>

// PolynomialFlowRegularizer — quadratic-basis least squares residual MSE.
// flow: (B=64, C=2, H=512, W=512) f32. Output: scalar f32.
//
// err(b,c) = ( Σ f² − rᵀ G⁻¹ r ) / N,  r_k = Σ basis_k(n)·f(n),
// G = BᵀB analytic (separable moments of linspace(-1,1,512)).
// out = (1/B) Σ_{b,c} err(b,c)
//
// SINGLE fused kernel: every block reduces one (channel, slice) and writes 7
// partials; the last block to finish (fence+counter) folds partials, solves
// the 6x6 per channel, and writes the scalar. Counter self-resets → graph-
// replay deterministic. Each thread owns a FIXED column group so all
// x-dependent terms are loop-invariant; only y varies across iterations.

#define B_  64
#define C_  2
#define H_  512
#define W_  512
#define BC_ (B_ * C_)                 // 128
#define N_  (H_ * W_)                 // 262144
#define SLICES 16
#define ROWS_PER_SLICE (H_ / SLICES)  // 32
#define THREADS 256
#define NBLOCKS (BC_ * SLICES)        // 2048
#define VECS_PER_ROW (W_ / 4)         // 128

// Per-block partials: [bc][slice][7]. Fully rewritten every launch.
__device__ float g_part[BC_ * SLICES * 7];
__device__ unsigned int g_count;      // zero-init; self-resets each launch

__global__ __launch_bounds__(THREADS)
void pfr_fused_kernel(const float* __restrict__ flow, float* __restrict__ out) {
    const int bc    = blockIdx.x;
    const int slice = blockIdx.y;
    const float4* __restrict__ p =
        (const float4*)(flow + (size_t)bc * N_ + (size_t)slice * ROWS_PER_SLICE * W_);

    const float inv = 2.0f / (float)(W_ - 1);   // grid step (H_ == W_)

    // Fixed column group for this thread (loop-invariant x values)
    const int colv = threadIdx.x & (VECS_PER_ROW - 1);     // vec-column 0..127
    const int row0 = threadIdx.x >> 7;                     // starting row 0..1
    const float x0 = fmaf((float)(colv << 2), inv, -1.0f);
    const float x1 = x0 + inv;
    const float x2 = x1 + inv;
    const float x3 = x2 + inv;

    // s[0]=Σf², s[1..6]=r for basis order [1, x, y, x², xy, y²]
    float s0 = 0.f, s1 = 0.f, s2 = 0.f, s3 = 0.f, s4 = 0.f, s5 = 0.f, s6 = 0.f;

    const float ybase = fmaf((float)(slice * ROWS_PER_SLICE), inv, -1.0f);

    // 16 iterations/thread, stride 2 rows; unroll 8 → MLP≈8 LDG.128 in flight
    #pragma unroll 8
    for (int rr = row0; rr < ROWS_PER_SLICE; rr += 2) {
        float4 v = p[rr * VECS_PER_ROW + colv];
        float y = fmaf((float)rr, inv, ybase);

        float sff  = fmaf(v.x, v.x, fmaf(v.y, v.y, fmaf(v.z, v.z, v.w * v.w)));
        float sf   = (v.x + v.y) + (v.z + v.w);
        float sxf  = fmaf(v.x, x0, fmaf(v.y, x1, fmaf(v.z, x2, v.w * x3)));
        float sx2f = fmaf(v.x * x0, x0, fmaf(v.y * x1, x1,
                     fmaf(v.z * x2, x2, (v.w * x3) * x3)));

        s0 += sff;
        s1 += sf;
        s2 += sxf;
        s3 = fmaf(y, sf,   s3);     // Σ y f
        s4 += sx2f;                 // Σ x² f
        s5 = fmaf(y, sxf,  s5);     // Σ x y f
        s6 = fmaf(y * y, sf, s6);   // Σ y² f
    }

    float s[7] = {s0, s1, s2, s3, s4, s5, s6};

    // warp reduce all 7
    #pragma unroll
    for (int k = 0; k < 7; k++) {
        #pragma unroll
        for (int o = 16; o > 0; o >>= 1)
            s[k] += __shfl_xor_sync(0xffffffffu, s[k], o);
    }

    __shared__ float shw[THREADS / 32][7];
    int warp = threadIdx.x >> 5;
    int lane = threadIdx.x & 31;
    if (lane == 0) {
        #pragma unroll
        for (int k = 0; k < 7; k++) shw[warp][k] = s[k];
    }
    __syncthreads();

    __shared__ bool is_last;
    if (threadIdx.x == 0) {
        float* dst = &g_part[(bc * SLICES + slice) * 7];
        #pragma unroll
        for (int k = 0; k < 7; k++) {
            float acc = 0.f;
            #pragma unroll
            for (int w = 0; w < THREADS / 32; w++) acc += shw[w][k];
            dst[k] = acc;
        }
        __threadfence();                              // publish partials
        unsigned int prev = atomicAdd(&g_count, 1u);  // completion counter
        is_last = (prev == NBLOCKS - 1);
        if (is_last) g_count = 0;                     // reset for next replay
    }
    __syncthreads();
    if (!is_last) return;

    // ---- Final block: fold partials, solve 6x6 per channel, reduce ----
    __shared__ double shd[BC_];
    const int t = threadIdx.x;
    if (t < BC_) {
        double acc[7] = {0, 0, 0, 0, 0, 0, 0};
        for (int sl = 0; sl < SLICES; sl++) {
            const float* src = &g_part[(t * SLICES + sl) * 7];
            #pragma unroll
            for (int k = 0; k < 7; k++) acc[k] += (double)src[k];
        }
        double q0 = acc[0];
        double r[6];
        #pragma unroll
        for (int k = 0; k < 6; k++) r[k] = acc[k + 1];

        // 1D moments of linspace(-1, 1, 512), in double
        double Sx2 = 0.0, Sx4 = 0.0;
        for (int i = 0; i < W_; i++) {
            double x = -1.0 + 2.0 * (double)i / (double)(W_ - 1);
            double x2 = x * x;
            Sx2 += x2;
            Sx4 += x2 * x2;
        }

        const double Nn  = (double)N_;
        const double Hs2 = (double)H_ * Sx2;   // Σ x² = Σ y²
        const double Hs4 = (double)H_ * Sx4;   // Σ x⁴ = Σ y⁴
        const double S22 = Sx2 * Sx2;          // Σ x²y²

        // Gram for [1, x, y, x², xy, y²] (odd moments vanish)
        double A[6][7];
        #pragma unroll
        for (int i = 0; i < 6; i++) {
            #pragma unroll
            for (int j = 0; j < 7; j++) A[i][j] = 0.0;
        }
        A[0][0] = Nn;  A[0][3] = Hs2; A[0][5] = Hs2;
        A[3][0] = Hs2; A[5][0] = Hs2;
        A[1][1] = Hs2; A[2][2] = Hs2;
        A[3][3] = Hs4; A[5][5] = Hs4;
        A[3][5] = S22; A[5][3] = S22;
        A[4][4] = S22;
        #pragma unroll
        for (int i = 0; i < 6; i++) A[i][6] = r[i];

        // Gaussian elimination (G is SPD, well-conditioned)
        for (int kk = 0; kk < 6; kk++) {
            double piv = 1.0 / A[kk][kk];
            for (int j = kk; j < 7; j++) A[kk][j] *= piv;
            for (int i = kk + 1; i < 6; i++) {
                double m = A[i][kk];
                if (m != 0.0)
                    for (int j = kk; j < 7; j++) A[i][j] -= m * A[kk][j];
            }
        }
        double c[6];
        for (int i = 5; i >= 0; i--) {
            double a = A[i][6];
            for (int j = i + 1; j < 6; j++) a -= A[i][j] * c[j];
            c[i] = a;
        }

        double dot = 0.0;
        #pragma unroll
        for (int k = 0; k < 6; k++) dot += r[k] * c[k];

        shd[t] = (q0 - dot) / Nn;
    }
    __syncthreads();
    for (int o = BC_ / 2; o > 0; o >>= 1) {
        if (t < o) shd[t] += shd[t + o];
        __syncthreads();
    }
    if (t == 0) out[0] = (float)(shd[0] / (double)B_);
}

extern "C" void kernel_launch(void* const* d_in, const int* in_sizes, int n_in,
                              void* d_out, int out_size) {
    const float* flow = (const float*)d_in[0];
    float* out = (float*)d_out;
    (void)in_sizes; (void)n_in; (void)out_size;

    dim3 grid(BC_, SLICES);
    pfr_fused_kernel<<<grid, THREADS>>>(flow, out);
}

// round 16
// speedup vs baseline: 5.5885x; 5.5885x over previous
#include <cuda_runtime.h>

// PolynomialFlowRegularizer — quadratic-basis least squares residual MSE.
// flow: (B=64, C=2, H=512, W=512) f32. Output: scalar f32.
//
// err(b,c) = ( Σ f² − rᵀ G⁻¹ r ) / N,  r_k = Σ basis_k(n)·f(n)
// G = BᵀB analytic (separable moments of linspace(-1,1,512)) — ALL constants
// computed at COMPILE TIME; G⁻¹ applied via its analytic block inverse
// (3 decoupled scalars + one constexpr-inverted 3×3). No runtime FP64 loops,
// no divisions — R4 showed a serial FP64 tail costing ~265us on B300's
// nerfed FP64 pipe; this removes it.
//
// SINGLE fused kernel: every block reduces one (channel, slice) and writes 7
// partials; the last block (fence+counter, self-resetting) folds partials and
// evaluates the closed-form quadratic residual.

#define B_  64
#define C_  2
#define H_  512
#define W_  512
#define BC_ (B_ * C_)                 // 128
#define N_  (H_ * W_)                 // 262144
#define SLICES 32
#define ROWS_PER_SLICE (H_ / SLICES)  // 16
#define THREADS 256
#define NBLOCKS (BC_ * SLICES)        // 4096
#define VECS_PER_ROW (W_ / 4)         // 128

// ---- Compile-time Gram constants (exact integer power sums, m = W-1) ----
constexpr double d_m  = (double)(W_ - 1);           // 511
constexpr double d_n  = (double)W_;                 // 512
constexpr double PS1  = d_m * (d_m + 1.0) / 2.0;
constexpr double PS2  = d_m * (d_m + 1.0) * (2.0 * d_m + 1.0) / 6.0;
constexpr double PS3  = PS1 * PS1;
constexpr double PS4  = d_m * (d_m + 1.0) * (2.0 * d_m + 1.0)
                        * (3.0 * d_m * d_m + 3.0 * d_m - 1.0) / 30.0;
constexpr double hh   = 2.0 / d_m;
// Σ x_i^2 and Σ x_i^4 over linspace(-1,1,512)
constexpr double Sx2  = d_n - 2.0 * hh * PS1 + hh * hh * PS2;
constexpr double Sx4  = d_n - 4.0 * hh * PS1 + 6.0 * hh * hh * PS2
                        - 4.0 * hh * hh * hh * PS3 + hh * hh * hh * hh * PS4;
constexpr double Nn   = d_n * d_n;                  // Σ 1
constexpr double Hs2  = d_n * Sx2;                  // Σ x² = Σ y²
constexpr double Hs4  = d_n * Sx4;                  // Σ x⁴ = Σ y⁴
constexpr double S22  = Sx2 * Sx2;                  // Σ x²y²
// Analytic inverse of the 3×3 block [[Nn,Hs2,Hs2],[Hs2,Hs4,S22],[Hs2,S22,Hs4]]
constexpr double DET3 = Nn * (Hs4 * Hs4 - S22 * S22)
                        - 2.0 * Hs2 * Hs2 * (Hs4 - S22);
constexpr double I00  = (Hs4 * Hs4 - S22 * S22) / DET3;
constexpr double I01  = -Hs2 * (Hs4 - S22) / DET3;
constexpr double I11  = (Nn * Hs4 - Hs2 * Hs2) / DET3;
constexpr double I12  = (Hs2 * Hs2 - Nn * S22) / DET3;
constexpr double INV_HS2 = 1.0 / Hs2;
constexpr double INV_S22 = 1.0 / S22;
constexpr double SCALE   = 1.0 / (Nn * (double)B_);   // fold 1/N and 1/B

// Per-block partials: [bc][slice][7]. Fully rewritten every launch.
__device__ float g_part[BC_ * SLICES * 7];
__device__ unsigned int g_count;      // zero-init; self-resets each launch

__global__ __launch_bounds__(THREADS)
void pfr_fused_kernel(const float* __restrict__ flow, float* __restrict__ out) {
    const int bc    = blockIdx.x;
    const int slice = blockIdx.y;
    const float4* __restrict__ p =
        (const float4*)(flow + (size_t)bc * N_ + (size_t)slice * ROWS_PER_SLICE * W_);

    const float inv = 2.0f / (float)(W_ - 1);   // grid step (H_ == W_)

    // Fixed column group for this thread (loop-invariant x values)
    const int colv = threadIdx.x & (VECS_PER_ROW - 1);     // vec-column 0..127
    const int row0 = threadIdx.x >> 7;                     // starting row 0..1
    const float x0 = fmaf((float)(colv << 2), inv, -1.0f);
    const float x1 = x0 + inv;
    const float x2 = x1 + inv;
    const float x3 = x2 + inv;

    // s0=Σf², then r for basis order [1, x, y, x², xy, y²]
    float s0 = 0.f, s1 = 0.f, s2 = 0.f, s3 = 0.f, s4 = 0.f, s5 = 0.f, s6 = 0.f;

    const float ybase = fmaf((float)(slice * ROWS_PER_SLICE), inv, -1.0f);

    // 8 iterations/thread, stride 2 rows; two batches of 4 LDG.128 in flight
    // (MLP 4, regs ~44-48 → 5 CTAs/SM, no spill risk)
    #pragma unroll 4
    for (int rr = row0; rr < ROWS_PER_SLICE; rr += 2) {
        float4 v = p[rr * VECS_PER_ROW + colv];
        float y = fmaf((float)rr, inv, ybase);

        float sff  = fmaf(v.x, v.x, fmaf(v.y, v.y, fmaf(v.z, v.z, v.w * v.w)));
        float sf   = (v.x + v.y) + (v.z + v.w);
        float sxf  = fmaf(v.x, x0, fmaf(v.y, x1, fmaf(v.z, x2, v.w * x3)));
        float sx2f = fmaf(v.x * x0, x0, fmaf(v.y * x1, x1,
                     fmaf(v.z * x2, x2, (v.w * x3) * x3)));

        s0 += sff;
        s1 += sf;
        s2 += sxf;
        s3 = fmaf(y, sf,   s3);     // Σ y f
        s4 += sx2f;                 // Σ x² f
        s5 = fmaf(y, sxf,  s5);     // Σ x y f
        s6 = fmaf(y * y, sf, s6);   // Σ y² f
    }

    float s[7] = {s0, s1, s2, s3, s4, s5, s6};

    // warp reduce all 7
    #pragma unroll
    for (int k = 0; k < 7; k++) {
        #pragma unroll
        for (int o = 16; o > 0; o >>= 1)
            s[k] += __shfl_xor_sync(0xffffffffu, s[k], o);
    }

    __shared__ float shw[THREADS / 32][7];
    int warp = threadIdx.x >> 5;
    int lane = threadIdx.x & 31;
    if (lane == 0) {
        #pragma unroll
        for (int k = 0; k < 7; k++) shw[warp][k] = s[k];
    }
    __syncthreads();

    __shared__ bool is_last;
    if (threadIdx.x == 0) {
        float* dst = &g_part[(bc * SLICES + slice) * 7];
        #pragma unroll
        for (int k = 0; k < 7; k++) {
            float acc = 0.f;
            #pragma unroll
            for (int w = 0; w < THREADS / 32; w++) acc += shw[w][k];
            dst[k] = acc;
        }
        __threadfence();                              // publish partials
        unsigned int prev = atomicAdd(&g_count, 1u);  // completion counter
        is_last = (prev == NBLOCKS - 1);
        if (is_last) g_count = 0;                     // reset for next replay
    }
    __syncthreads();
    if (!is_last) return;

    // ---- Final block: fold partials, closed-form residual per channel ----
    __shared__ double shd[BC_ / 32];   // per-warp partial of channel sums
    const int t = threadIdx.x;
    double e = 0.0;
    if (t < BC_) {
        // Fold the slice-partials (contiguous 7*SLICES floats per channel)
        double a0 = 0, a1 = 0, a2 = 0, a3 = 0, a4 = 0, a5 = 0, a6 = 0;
        const float* src = &g_part[t * SLICES * 7];
        #pragma unroll 8
        for (int sl = 0; sl < SLICES; sl++) {
            a0 += (double)src[sl * 7 + 0];
            a1 += (double)src[sl * 7 + 1];
            a2 += (double)src[sl * 7 + 2];
            a3 += (double)src[sl * 7 + 3];
            a4 += (double)src[sl * 7 + 4];
            a5 += (double)src[sl * 7 + 5];
            a6 += (double)src[sl * 7 + 6];
        }
        // r = [a1..a6] for basis [1, x, y, x², xy, y²]; a0 = Σf²
        // dot = rᵀ G⁻¹ r via analytic block inverse:
        //   decoupled: x, y, xy rows; coupled 3×3 over [1, x², y²] = [a1,a4,a6]
        double dot = (a2 * a2 + a3 * a3) * INV_HS2   // x, y rows
                   + (a5 * a5) * INV_S22             // xy row
                   + I00 * a1 * a1
                   + I11 * (a4 * a4 + a6 * a6)
                   + 2.0 * I01 * a1 * (a4 + a6)
                   + 2.0 * I12 * a4 * a6;
        e = a0 - dot;
    }
    // warp-level double reduction (lo/hi word shuffles)
    #pragma unroll
    for (int o = 16; o > 0; o >>= 1) {
        int lo = __double2loint(e), hi = __double2hiint(e);
        lo = __shfl_xor_sync(0xffffffffu, lo, o);
        hi = __shfl_xor_sync(0xffffffffu, hi, o);
        e += __hiloint2double(hi, lo);
    }
    if ((t & 31) == 0 && t < BC_) shd[t >> 5] = e;
    __syncthreads();
    if (t == 0) {
        double total = 0.0;
        #pragma unroll
        for (int w = 0; w < BC_ / 32; w++) total += shd[w];
        out[0] = (float)(total * SCALE);
    }
}

extern "C" void kernel_launch(void* const* d_in, const int* in_sizes, int n_in,
                              void* d_out, int out_size) {
    const float* flow = (const float*)d_in[0];
    float* out = (float*)d_out;
    (void)in_sizes; (void)n_in; (void)out_size;

    dim3 grid(BC_, SLICES);
    pfr_fused_kernel<<<grid, THREADS>>>(flow, out);
}